// round 3
// baseline (speedup 1.0000x reference)
#include <cuda_runtime.h>
#include <cuda_bf16.h>
#include <cstdint>

// token_reprs: [B=32, L=512, H=768] f32 ; pos_idx: [B,E=32,M=8,S=4] i32
// out f32: entity [B,E,H] @0 ; mentions [B,E,M,H] @786432 ; mask [B,E,M] @7077888

#define B_ 32
#define L_ 512
#define H_ 768
#define E_ 32
#define M_ 8
#define S_ 4
#define HV (H_ / 4)          // 192 float4 per row

__global__ __launch_bounds__(HV)
void entity_repr_kernel(const float* __restrict__ tok,
                        const int* __restrict__ pos,
                        float* __restrict__ ent,
                        float* __restrict__ men,
                        float* __restrict__ mask)
{
    const int be = blockIdx.x;          // 0 .. B*E-1
    const int b  = be >> 5;             // E_ == 32

    __shared__ int sidx[M_ * S_];
    if (threadIdx.x < M_ * S_) {
        sidx[threadIdx.x] = pos[(size_t)be * (M_ * S_) + threadIdx.x];
    }
    __syncthreads();

    const int t = threadIdx.x;          // float4 column, 0..191
    const float4* __restrict__ tokb =
        reinterpret_cast<const float4*>(tok) + (size_t)b * L_ * HV;

    float4* __restrict__ men4 =
        reinterpret_cast<float4*>(men) + ((size_t)be * M_) * HV;
    float4* __restrict__ ent4 =
        reinterpret_cast<float4*>(ent) + (size_t)be * HV;

    float ex = 0.f, ey = 0.f, ez = 0.f, ew = 0.f;

    // Process mentions in pairs: 8 independent float4 gathers in flight (MLP=8)
    #pragma unroll
    for (int p = 0; p < M_ / 2; p++) {
        const int i0 = sidx[p * 8 + 0];
        const int i1 = sidx[p * 8 + 1];
        const int i2 = sidx[p * 8 + 2];
        const int i3 = sidx[p * 8 + 3];
        const int i4 = sidx[p * 8 + 4];
        const int i5 = sidx[p * 8 + 5];
        const int i6 = sidx[p * 8 + 6];
        const int i7 = sidx[p * 8 + 7];

        const float4 v0 = __ldg(&tokb[(size_t)i0 * HV + t]);
        const float4 v1 = __ldg(&tokb[(size_t)i1 * HV + t]);
        const float4 v2 = __ldg(&tokb[(size_t)i2 * HV + t]);
        const float4 v3 = __ldg(&tokb[(size_t)i3 * HV + t]);
        const float4 v4 = __ldg(&tokb[(size_t)i4 * HV + t]);
        const float4 v5 = __ldg(&tokb[(size_t)i5 * HV + t]);
        const float4 v6 = __ldg(&tokb[(size_t)i6 * HV + t]);
        const float4 v7 = __ldg(&tokb[(size_t)i7 * HV + t]);

        float4 r0, r1;
        r0.x = (v0.x + v1.x + v2.x + v3.x) * 0.25f;
        r0.y = (v0.y + v1.y + v2.y + v3.y) * 0.25f;
        r0.z = (v0.z + v1.z + v2.z + v3.z) * 0.25f;
        r0.w = (v0.w + v1.w + v2.w + v3.w) * 0.25f;
        r1.x = (v4.x + v5.x + v6.x + v7.x) * 0.25f;
        r1.y = (v4.y + v5.y + v6.y + v7.y) * 0.25f;
        r1.z = (v4.z + v5.z + v6.z + v7.z) * 0.25f;
        r1.w = (v4.w + v5.w + v6.w + v7.w) * 0.25f;

        __stcs(&men4[(size_t)(2 * p + 0) * HV + t], r0);
        __stcs(&men4[(size_t)(2 * p + 1) * HV + t], r1);

        ex += r0.x + r1.x;
        ey += r0.y + r1.y;
        ez += r0.z + r1.z;
        ew += r0.w + r1.w;
    }

    float4 er;
    er.x = ex * 0.125f; er.y = ey * 0.125f;
    er.z = ez * 0.125f; er.w = ew * 0.125f;
    __stcs(&ent4[t], er);

    if (t < M_) {
        mask[(size_t)be * M_ + t] = 1.0f;
    }
}

extern "C" void kernel_launch(void* const* d_in, const int* in_sizes, int n_in,
                              void* d_out, int out_size)
{
    const float* tok = (const float*)d_in[0];
    const int*   pos = (const int*)d_in[1];

    float* out = (float*)d_out;
    float* ent  = out;                                  // 786432
    float* men  = out + (size_t)B_ * E_ * H_;           // +786432
    float* mask = men + (size_t)B_ * E_ * M_ * H_;      // +6291456

    entity_repr_kernel<<<B_ * E_, HV>>>(tok, pos, ent, men, mask);
}